// round 6
// baseline (speedup 1.0000x reference)
#include <cuda_runtime.h>
#include <cstdint>

// ---------------------------------------------------------------------------
// StableSpikingCoreFlow: T=64, B=128, D=N=2048, L=4, OUT=1024
//
// Identity: mean_t(gathered_t @ W^T) = (mean_t gathered_t) @ W^T; next layer
// consumes mean_t(spikes) = count/64 (dyadic -> exact). Output = total spike
// counts at out_idx.
//
// Round 6: 1024 threads (32 warps/SM, 8/SMSP), 8 split-K groups of 128
// threads, per-thread 2m x 8n fma.rn.f32x2 tile (32 acc regs -> fits the
// 64-reg cap), cp.async double-buffered BK=8 tiles. Summation structure is
// bit-identical to round 5 (KSLICE=256, flush at 128 k, 64-term even/odd
// chains, tree-16 merge) -> rel_err 0.0 preserved.
// ---------------------------------------------------------------------------

#define Bc   128
#define Dc   2048
#define Nc   2048
#define Tc   64
#define Lc   4
#define OUTc 1024

#define BM 32
#define BN 64
#define BK 8
#define NTHREADS 1024
#define NGROUPS 8               // 128 threads (4 warps) per group
#define KSLICE (Dc / NGROUPS)   // 256
#define NKB (KSLICE / BK)       // 32 tiles per group

// smem tiles: rows hold BK=8 k-floats (32B), padded to 48B (12 floats);
// 16B-granule offsets 48*r mod 128 are all distinct -> conflict-free LDS.128.
#define ROWF 12
#define AS_SZ (BM * ROWF)        // 384 floats
#define BS_SZ (BN * ROWF)        // 768 floats
#define TILE_SZ (AS_SZ + BS_SZ)  // 1152 floats per group per buffer
#define PS_OFF (2 * NGROUPS * TILE_SZ)             // 18432 floats
#define NPLANES 16                                  // 8 groups x 2 k-halves
#define SMEM_FLOATS (PS_OFF + NPLANES * BM * BN)    // 51200
#define SMEM_BYTES (SMEM_FLOATS * 4)                // 204800

// scratch (no cudaMalloc allowed)
__device__ float g_G [Bc * Dc];
__device__ float g_R0[Bc * Nc];
__device__ float g_R1[Bc * Nc];

// ---------------------------------------------------------------------------
__device__ __forceinline__ void cp16(uint32_t dst, const float* src) {
    asm volatile("cp.async.cg.shared.global [%0], [%1], 16;\n"
                 :: "r"(dst), "l"(src));
}
#define CP_COMMIT() asm volatile("cp.async.commit_group;\n" ::: "memory")
#define CP_WAIT(n)  asm volatile("cp.async.wait_group %0;\n" :: "n"(n) : "memory")

__device__ __forceinline__ void ffma2(unsigned long long& c,
                                      unsigned long long a,
                                      unsigned long long b) {
    asm volatile("fma.rn.f32x2 %0, %1, %2, %0;\n" : "+l"(c) : "l"(a), "l"(b));
}

__device__ __forceinline__ float pair_sum(unsigned long long v) {
    float lo = __uint_as_float((unsigned)v);
    float hi = __uint_as_float((unsigned)(v >> 32));
    return __fadd_rn(lo, hi);
}

// exact fp32 semantics of the reference spike scan
__device__ __forceinline__ float spike_rate(float a, float thr) {
    int c;
    if (a <= 0.f) {
        c = 0;                       // thr > 0: m never exceeds thr
    } else if (a > thr) {
        c = Tc;                      // spikes every step, exactly
    } else {
        float m = 0.f; c = 0;
        for (int t = 0; t < Tc; t++) {
            m += a;
            if (m > thr) { m -= thr; c++; }
        }
    }
    return (float)c * (1.0f / Tc);
}

// ---------------------------------------------------------------------------
__global__ void gather_kernel(const float* __restrict__ Rin,
                              const int*   __restrict__ axon,
                              float*       __restrict__ G)
{
    int idx = blockIdx.x * blockDim.x + threadIdx.x;
    if (idx >= Bc * Dc) return;
    int b = idx >> 11;
    int a = idx & 2047;
    G[idx] = Rin[(b << 11) + axon[a]];
}

// ---------------------------------------------------------------------------
__global__ __launch_bounds__(NTHREADS, 1)
void layer_kernel(const float* __restrict__ G,     // [B, D]
                  const float* __restrict__ W,     // [N, D] row-major
                  const float* __restrict__ thresholds,
                  int l,
                  float* __restrict__ Rout)        // [B, N] rates = c/64
{
    extern __shared__ float sm[];

    const int tid  = threadIdx.x;
    const int g    = tid >> 7;           // split-K group 0..7 (4 warps)
    const int gt   = tid & 127;
    const int w    = gt >> 5;            // warp within group 0..3
    const int lane = gt & 31;
    const int ncol = lane & 7;           // n base 0..7
    const int mrow = lane >> 3;          // 0..3
    const int m0   = (w * 4 + mrow) * 2; // 0,2,...,30

    const int bm = blockIdx.y * BM;
    const int bn = blockIdx.x * BN;
    const int kbase = g * KSLICE;

    float* As0 = sm + (0 * NGROUPS + g) * TILE_SZ;
    float* As1 = sm + (1 * NGROUPS + g) * TILE_SZ;
    float* Bs0 = As0 + AS_SZ;
    float* Bs1 = As1 + AS_SZ;
    float* Ps  = sm + PS_OFF;

    // cp.async mapping: every thread 1 B chunk; first 64 threads also 1 A chunk
    const int brow = gt >> 1;            // 0..63
    const int bch  = gt & 1;             // 16B chunk
    const int arow = (gt & 63) >> 1;     // 0..31
    const int ach  = gt & 1;
    const bool doA = (gt < 64);

    const float* gB = W + (size_t)(bn + brow) * Dc + kbase + bch * 4;
    const float* gA = G + (size_t)(bm + arow) * Dc + kbase + ach * 4;

    const uint32_t sB0 = (uint32_t)__cvta_generic_to_shared(Bs0 + brow * ROWF + bch * 4);
    const uint32_t sB1 = (uint32_t)__cvta_generic_to_shared(Bs1 + brow * ROWF + bch * 4);
    const uint32_t sA0 = (uint32_t)__cvta_generic_to_shared(As0 + arow * ROWF + ach * 4);
    const uint32_t sA1 = (uint32_t)__cvta_generic_to_shared(As1 + arow * ROWF + ach * 4);

#define ISSUE(t, buf) do { \
        cp16((buf) ? sB1 : sB0, gB + (t) * BK); \
        if (doA) cp16((buf) ? sA1 : sA0, gA + (t) * BK); \
        CP_COMMIT(); \
    } while (0)

    // 16 packed accumulators: acc[i][j] = f32x2 (even-k, odd-k chains)
    // for output (m = m0 + i, n = ncol + 8j)
    unsigned long long acc[2][8];
#pragma unroll
    for (int i = 0; i < 2; i++)
#pragma unroll
        for (int j = 0; j < 8; j++) acc[i][j] = 0ull;

    ISSUE(0, 0);
    ISSUE(1, 1);

    for (int t = 0; t < NKB; t++) {
        if (t == NKB - 1) { CP_WAIT(0); } else { CP_WAIT(1); }
        __syncthreads();

        const float* As = (t & 1) ? As1 : As0;
        const float* Bs = (t & 1) ? Bs1 : Bs0;

#pragma unroll
        for (int h = 0; h < 2; h++) {
            ulonglong2 a0 = *reinterpret_cast<const ulonglong2*>(
                                As + (m0 + 0) * ROWF + h * 4);
            ulonglong2 a1 = *reinterpret_cast<const ulonglong2*>(
                                As + (m0 + 1) * ROWF + h * 4);
#pragma unroll
            for (int j = 0; j < 8; j++) {
                ulonglong2 b = *reinterpret_cast<const ulonglong2*>(
                                   Bs + (ncol + 8 * j) * ROWF + h * 4);
                ffma2(acc[0][j], a0.x, b.x);
                ffma2(acc[0][j], a0.y, b.y);
                ffma2(acc[1][j], a1.x, b.x);
                ffma2(acc[1][j], a1.y, b.y);
            }
        }
        __syncthreads();
        if (t + 2 < NKB) ISSUE(t + 2, t & 1);

        // flush first k-half (128 k -> 64-term chains) to partial plane g
        if (t == NKB / 2 - 1) {
#pragma unroll
            for (int i = 0; i < 2; i++)
#pragma unroll
                for (int j = 0; j < 8; j++) {
                    Ps[g * (BM * BN) + (m0 + i) * BN + (ncol + 8 * j)] =
                        pair_sum(acc[i][j]);
                    acc[i][j] = 0ull;
                }
        }
    }
#undef ISSUE

    // flush second k-half to plane 8+g
#pragma unroll
    for (int i = 0; i < 2; i++)
#pragma unroll
        for (int j = 0; j < 8; j++)
            Ps[(NGROUPS + g) * (BM * BN) + (m0 + i) * BN + (ncol + 8 * j)] =
                pair_sum(acc[i][j]);
    __syncthreads();

    // tree-16 merge + fused spike scan, 2 outputs per thread
    {
        const int idx = tid * 2;
        const int m = idx >> 6;
        const int n = idx & 63;

        float2 v[NPLANES];
#pragma unroll
        for (int p = 0; p < NPLANES; p++)
            v[p] = *(const float2*)&Ps[p * (BM * BN) + idx];

        float ex[NPLANES], ey[NPLANES];
#pragma unroll
        for (int p = 0; p < NPLANES; p++) { ex[p] = v[p].x; ey[p] = v[p].y; }
        // fixed-order pairwise tree
#pragma unroll
        for (int s = 1; s < NPLANES; s <<= 1)
#pragma unroll
            for (int p = 0; p < NPLANES; p += 2 * s) {
                ex[p] = __fadd_rn(ex[p], ex[p + s]);
                ey[p] = __fadd_rn(ey[p], ey[p + s]);
            }

        const float thr = thresholds[l];
        float2 outv;
        outv.x = spike_rate(ex[0], thr);
        outv.y = spike_rate(ey[0], thr);
        *(float2*)&Rout[(bm + m) * Nc + bn + n] = outv;
    }
}

// ---------------------------------------------------------------------------
__global__ void out_kernel(const float* __restrict__ R,
                           const int*   __restrict__ out_idx,
                           float*       __restrict__ out)
{
    int idx = blockIdx.x * blockDim.x + threadIdx.x;
    if (idx >= Bc * OUTc) return;
    int b = idx >> 10;
    int o = idx & 1023;
    out[idx] = R[(b << 11) + out_idx[o]] * (float)Tc;  // rate*64 = count, exact
}

// ---------------------------------------------------------------------------
extern "C" void kernel_launch(void* const* d_in, const int* in_sizes, int n_in,
                              void* d_out, int out_size)
{
    const float* x       = (const float*)d_in[0];   // [B, D]
    const float* W       = (const float*)d_in[1];   // [L, N, D]
    const float* thr     = (const float*)d_in[2];   // [L]
    const int*   axon    = (const int*)  d_in[3];   // [L, D]
    const int*   out_idx = (const int*)  d_in[4];   // [OUT]
    (void)in_sizes; (void)n_in; (void)out_size;

    cudaFuncSetAttribute(layer_kernel,
                         cudaFuncAttributeMaxDynamicSharedMemorySize,
                         SMEM_BYTES);

    float *G, *R0, *R1;
    cudaGetSymbolAddress((void**)&G,  g_G);
    cudaGetSymbolAddress((void**)&R0, g_R0);
    cudaGetSymbolAddress((void**)&R1, g_R1);
    float* bufs[2] = { R0, R1 };

    dim3 ggrid((Bc * Dc + 255) / 256);
    dim3 lgrid(Nc / BN, Bc / BM);   // (32, 4) = 128 blocks

    const float* rin = x;
    for (int l = 0; l < Lc; l++) {
        gather_kernel<<<ggrid, 256>>>(rin, axon + l * Dc, G);
        layer_kernel <<<lgrid, NTHREADS, SMEM_BYTES>>>(
            G, W + (size_t)l * Nc * Dc, thr, l, bufs[l & 1]);
        rin = bufs[l & 1];
    }
    out_kernel<<<(Bc * OUTc + 255) / 256, 256>>>(rin, out_idx, (float*)d_out);
}